// round 16
// baseline (speedup 1.0000x reference)
#include <cuda_runtime.h>
#include <math.h>

// IN_FEATURES=128, UNITS=512, BATCH=2048, out = [x (2048*128) ; logdet (2048)]
// O(n^2) MADE inverse, warp-per-2-rows: weight loads amortized across rows.
#define THREADS 256

typedef unsigned long long ull;

// ---- device scratch ----
__device__ float g_W1p[512 * 128];        // [p][j]  masked W1, hidden permuted
__device__ float g_W2q[512 * 512];        // [q][p]  masked W2 (scalar path, i<4)
__device__ float g_W2zf[256 * 512 * 2];   // [q/2][p]{q0,q1} paired columns
__device__ float g_W3zf[128 * 512 * 2];   // [o][q]{mu,sig} paired
__device__ float g_b1p[512];
__device__ float g_b2p[512];

__device__ __forceinline__ int posOf(int k) {
    int d = k % 127;
    int j = k / 127;
    return d * 4 + (d < 4 ? d : 4) + j;
}

// ---------------- prologue: mask + permute + repack ----------------
__global__ void k_transform(const float* __restrict__ W1, const float* __restrict__ b1,
                            const float* __restrict__ W2, const float* __restrict__ b2,
                            const float* __restrict__ W3,
                            const float* __restrict__ m1, const float* __restrict__ m2,
                            const float* __restrict__ m3) {
    int idx = blockIdx.x * blockDim.x + threadIdx.x;
    int stride = gridDim.x * blockDim.x;
    for (int t = idx; t < 512 * 128; t += stride) {
        int k = t >> 7, i = t & 127;
        g_W1p[posOf(k) * 128 + i] = W1[t] * m1[t];
    }
    for (int t = idx; t < 512 * 512; t += stride) {
        int m = t >> 9, k = t & 511;
        float v = W2[t] * m2[t];
        int q = posOf(m), p = posOf(k);
        g_W2q[q * 512 + p] = v;
        g_W2zf[((q >> 1) * 512 + p) * 2 + (q & 1)] = v;
    }
    for (int t = idx; t < 256 * 512; t += stride) {
        int o = t >> 9, m = t & 511;
        float v = W3[t] * m3[t];
        int q = posOf(m);
        if (o < 128) g_W3zf[(o * 512 + q) * 2]             = v;
        else         g_W3zf[((o - 128) * 512 + q) * 2 + 1] = v;
    }
    for (int t = idx; t < 512; t += stride) {
        g_b1p[posOf(t)] = b1[t];
        g_b2p[posOf(t)] = b2[t];
    }
}

// ---- packed f32x2 helpers ----
__device__ __forceinline__ ull dup2(float w) {
    ull r; asm("mov.b64 %0, {%1, %1};" : "=l"(r) : "f"(w)); return r;
}
__device__ __forceinline__ ull mk2(unsigned lo, unsigned hi) {
    ull r; asm("mov.b64 %0, {%1, %2};" : "=l"(r) : "r"(lo), "r"(hi)); return r;
}
__device__ __forceinline__ float2 u2f(ull v) {
    float2 f; asm("mov.b64 {%0, %1}, %2;" : "=f"(f.x), "=f"(f.y) : "l"(v)); return f;
}
__device__ __forceinline__ void pfma(ull& acc, ull w, ull v) {
    asm("fma.rn.f32x2 %0, %1, %2, %0;" : "+l"(acc) : "l"(w), "l"(v));
}
__device__ __forceinline__ void addp(ull& a, ull b) {
    asm("add.rn.f32x2 %0, %0, %1;" : "+l"(a) : "l"(b));
}

// smem per-row layout (floats)
#define OFF_H1 0
#define OFF_H2 512
#define OFF_X  1024
#define OFF_U  1152
#define SR     1288      // row stride (floats); SR*4 divisible by 16

// ---------------- main kernel: 128 CTAs x 8 warps, warp = 2 rows ----------------
__global__ void __launch_bounds__(THREADS, 1)
k_main(const float* __restrict__ u, const float* __restrict__ b3,
       float* __restrict__ out) {
    extern __shared__ float sm[];
    float* b3s = sm + 16 * SR;          // 256 floats
    const int tid  = threadIdx.x;
    const int lane = tid & 31;
    const int w    = tid >> 5;          // warp id -> rows 2w, 2w+1
    const int row0 = blockIdx.x * 16;
    const int rA   = 2 * w, rB = 2 * w + 1;

    float* h1A = sm + rA * SR + OFF_H1;  float* h1B = sm + rB * SR + OFF_H1;
    float* h2A = sm + rA * SR + OFF_H2;  float* h2B = sm + rB * SR + OFF_H2;
    float* xrA = sm + rA * SR + OFF_X;   float* xrB = sm + rB * SR + OFF_X;
    float* urA = sm + rA * SR + OFF_U;   float* urB = sm + rB * SR + OFF_U;

    // zero h1/h2/x (products past prefix use zero weights; garbage never read)
    for (int t = tid; t < 16 * 1152; t += THREADS) {
        int r = t / 1152, o = t - r * 1152;
        sm[r * SR + o] = 0.f;
    }
    for (int t = tid; t < 16 * 128; t += THREADS) {
        int r = t >> 7, c = t & 127;
        sm[r * SR + OFF_U + c] = u[(row0 + r) * 128 + c];
    }
    if (tid < 256) b3s[tid] = b3[tid];
    float ldA = 0.f, ldB = 0.f;
    __syncthreads();

    const ull* W2z = (const ull*)g_W2zf;

    for (int i = 0; i < 128; ++i) {
        const int s_i = 4 * i + (i < 4 ? i : 4);

        // ---- prefetch next step's weight rows into L1 (one warp) ----
        if (w == (i & 7) && i + 1 < 128) {
            int ip = i + 1;
            int s_nn = 4 * ip + (ip < 4 ? ip : 4);
            const char* w3p = (const char*)((const ull*)g_W3zf + (size_t)ip * 512);
            asm volatile("prefetch.global.L1 [%0];" :: "l"(w3p + lane * 128));
            const char* w2p = (const char*)g_W2zf + (size_t)s_nn * 2048;
            asm volatile("prefetch.global.L1 [%0];" :: "l"(w2p + lane * 128));
            asm volatile("prefetch.global.L1 [%0];" :: "l"(w2p + 4096 + lane * 128));
            const char* w1p = (const char*)(g_W1p + (size_t)s_nn * 128);
            if (lane < 16)
                asm volatile("prefetch.global.L1 [%0];" :: "l"(w1p + lane * 128));
        }

        // ---- Z: (mu_i, sigma_i) for both rows; weights loaded once ----
        {
            ull aA0 = 0ull, aA1 = 0ull, aB0 = 0ull, aB1 = 0ull;
            const uint4* wz4 = (const uint4*)((const ull*)g_W3zf + (size_t)i * 512);
            const int nG = (s_i + 255) >> 8;   // <= 2
            for (int g = 0; g < nG; ++g) {
                uint4 wv[4]; float2 hA[4], hB[4];
#pragma unroll
                for (int b = 0; b < 4; ++b) {
                    int idx = lane + ((g * 4 + b) << 5);
                    wv[b] = __ldg(wz4 + idx);
                    hA[b] = *(const float2*)(h2A + 2 * idx);
                    hB[b] = *(const float2*)(h2B + 2 * idx);
                }
#pragma unroll
                for (int b = 0; b < 4; ++b) {
                    ull wlo = mk2(wv[b].x, wv[b].y), whi = mk2(wv[b].z, wv[b].w);
                    pfma(aA0, wlo, dup2(hA[b].x)); pfma(aA1, whi, dup2(hA[b].y));
                    pfma(aB0, wlo, dup2(hB[b].x)); pfma(aB1, whi, dup2(hB[b].y));
                }
            }
            addp(aA0, aA1); addp(aB0, aB1);
#pragma unroll
            for (int off = 16; off >= 1; off >>= 1) {
                addp(aA0, __shfl_xor_sync(0xffffffffu, aA0, off));
                addp(aB0, __shfl_xor_sync(0xffffffffu, aB0, off));
            }
            float2 mA = u2f(aA0), mB = u2f(aB0);
            float sgA = mA.y + b3s[i + 128], sgB = mB.y + b3s[i + 128];
            float xA = urA[i] * __expf(sgA) + (mA.x + b3s[i]);
            float xB = urB[i] * __expf(sgB) + (mB.x + b3s[i]);
            if (lane == 0) {
                xrA[i] = xA; xrB[i] = xB;
                ldA += sgA;  ldB += sgB;
            }
        }
        __syncwarp();
        if (i == 127) break;

        const int nd  = (i < 4) ? 5 : 4;
        const int s_n = s_i + nd;

        // ---- H1: new layer-1 cols; 8 lanes/col, weights shared across rows ----
        {
            int g8 = lane >> 3, sp = lane & 7;
            int len = i + 1;
            int nG = (len + 63) >> 6;              // <= 2
            int nCols = (nd + 3) >> 2;             // 1 or 2 (uniform)
            const float4* xA4 = (const float4*)xrA;
            const float4* xB4 = (const float4*)xrB;
            for (int cc = 0; cc < nCols; ++cc) {
                int c  = cc * 4 + g8;
                int cA = c < nd ? c : nd - 1;
                int p  = s_i + cA;
                const float4* w1r = (const float4*)(g_W1p + p * 128);
                float aA = 0.f, aB = 0.f;
                for (int g = 0; g < nG; ++g) {
                    float4 wv[2], vA[2], vB[2];
#pragma unroll
                    for (int b = 0; b < 2; ++b) {
                        int idx = sp + ((g * 2 + b) << 3);
                        wv[b] = __ldg(w1r + idx);
                        vA[b] = xA4[idx];
                        vB[b] = xB4[idx];
                    }
#pragma unroll
                    for (int b = 0; b < 2; ++b) {
                        aA = fmaf(wv[b].x, vA[b].x, aA); aB = fmaf(wv[b].x, vB[b].x, aB);
                        aA = fmaf(wv[b].y, vA[b].y, aA); aB = fmaf(wv[b].y, vB[b].y, aB);
                        aA = fmaf(wv[b].z, vA[b].z, aA); aB = fmaf(wv[b].z, vB[b].z, aB);
                        aA = fmaf(wv[b].w, vA[b].w, aA); aB = fmaf(wv[b].w, vB[b].w, aB);
                    }
                }
#pragma unroll
                for (int off = 1; off <= 4; off <<= 1) {
                    aA += __shfl_xor_sync(0xffffffffu, aA, off);
                    aB += __shfl_xor_sync(0xffffffffu, aB, off);
                }
                if (sp == 0 && c < nd) {
                    h1A[p] = fmaxf(g_b1p[p] + aA, 0.f);
                    h1B[p] = fmaxf(g_b1p[p] + aB, 0.f);
                }
            }
        }
        __syncwarp();

        // ---- H2: new layer-2 cols ----
        if (i >= 4) {
            // q-pairs; 16 lanes/pair; weights shared across rows
            int h  = lane >> 4;
            int sp = lane & 15;
            const uint4* w2r = (const uint4*)(W2z + ((size_t)(s_i >> 1) + h) * 512);
            ull aA0 = 0ull, aA1 = 0ull, aB0 = 0ull, aB1 = 0ull;
            const int nG = (s_n + 127) >> 7;       // <= 4
            for (int g = 0; g < nG; ++g) {
                uint4 wv[4]; float2 hA[4], hB[4];
#pragma unroll
                for (int b = 0; b < 4; ++b) {
                    int idx = sp + ((g * 4 + b) << 4);
                    wv[b] = __ldg(w2r + idx);
                    hA[b] = *(const float2*)(h1A + 2 * idx);
                    hB[b] = *(const float2*)(h1B + 2 * idx);
                }
#pragma unroll
                for (int b = 0; b < 4; ++b) {
                    ull wlo = mk2(wv[b].x, wv[b].y), whi = mk2(wv[b].z, wv[b].w);
                    pfma(aA0, wlo, dup2(hA[b].x)); pfma(aA1, whi, dup2(hA[b].y));
                    pfma(aB0, wlo, dup2(hB[b].x)); pfma(aB1, whi, dup2(hB[b].y));
                }
            }
            addp(aA0, aA1); addp(aB0, aB1);
#pragma unroll
            for (int off = 8; off >= 1; off >>= 1) {
                addp(aA0, __shfl_xor_sync(0xffffffffu, aA0, off));
                addp(aB0, __shfl_xor_sync(0xffffffffu, aB0, off));
            }
            if (sp == 0) {
                float2 vA = u2f(aA0), vB = u2f(aB0);
                int q0 = s_i + 2 * h;
                float b0 = g_b2p[q0], b1v = g_b2p[q0 + 1];
                h2A[q0]     = fmaxf(b0 + vA.x, 0.f);
                h2A[q0 + 1] = fmaxf(b1v + vA.y, 0.f);
                h2B[q0]     = fmaxf(b0 + vB.x, 0.f);
                h2B[q0 + 1] = fmaxf(b1v + vB.y, 0.f);
            }
        } else {
            // scalar fallback (i<4, s_n<=20): 8 lanes/col
            int g8 = lane >> 3, sp = lane & 7;
            int nIter = (nd + 3) >> 2;
            for (int cc = 0; cc < nIter; ++cc) {
                int c  = cc * 4 + g8;
                int cA = c < nd ? c : nd - 1;
                int q  = s_i + cA;
                const float* w2row = g_W2q + q * 512;
                float aA = 0.f, aB = 0.f;
#pragma unroll
                for (int b = 0; b < 3; ++b) {
                    int p = sp + (b << 3);
                    float wv = __ldg(w2row + p);
                    aA = fmaf(wv, h1A[p], aA);
                    aB = fmaf(wv, h1B[p], aB);
                }
#pragma unroll
                for (int off = 1; off <= 4; off <<= 1) {
                    aA += __shfl_xor_sync(0xffffffffu, aA, off);
                    aB += __shfl_xor_sync(0xffffffffu, aB, off);
                }
                if (sp == 0 && c < nd) {
                    h2A[q] = fmaxf(g_b2p[q] + aA, 0.f);
                    h2B[q] = fmaxf(g_b2p[q] + aB, 0.f);
                }
            }
        }
        __syncwarp();
    }

    if (lane == 0) {
        out[2048 * 128 + row0 + rA] = ldA;
        out[2048 * 128 + row0 + rB] = ldB;
    }

    __syncthreads();
    for (int t = tid; t < 16 * 128; t += THREADS) {
        int r = t >> 7, c = t & 127;
        out[(row0 + r) * 128 + c] = sm[r * SR + OFF_X + c];
    }
}

extern "C" void kernel_launch(void* const* d_in, const int* in_sizes, int n_in,
                              void* d_out, int out_size) {
    const float* u  = (const float*)d_in[0];
    const float* W1 = (const float*)d_in[1];
    const float* b1 = (const float*)d_in[2];
    const float* W2 = (const float*)d_in[3];
    const float* b2 = (const float*)d_in[4];
    const float* W3 = (const float*)d_in[5];
    const float* b3 = (const float*)d_in[6];
    const float* m1 = (const float*)d_in[7];
    const float* m2 = (const float*)d_in[8];
    const float* m3 = (const float*)d_in[9];
    float* out = (float*)d_out;

    const size_t smem = (size_t)(16 * SR + 256) * sizeof(float); // 83456 B
    cudaFuncSetAttribute(k_main, cudaFuncAttributeMaxDynamicSharedMemorySize, (int)smem);

    k_transform<<<256, 256>>>(W1, b1, W2, b2, W3, m1, m2, m3);
    k_main<<<128, THREADS, smem>>>(u, b3, out);
}